// round 9
// baseline (speedup 1.0000x reference)
#include <cuda_runtime.h>

#define NROWS 4096
#define CDIM  512
#define BM 64
#define BN 64
#define BK 16

// Scratch (static device globals: no allocation anywhere)
__device__ float g_n[4][NROWS * CDIM];     // normalized: 0=vn 1=tn 2=pvn 3=ptn
__device__ float g_diag[2][NROWS];         // 0: diag(sv_raw), 1: diag(st_raw)
__device__ float g_rowSum[NROWS];          // sum_j exp(10*raw - 10) over BOTH matrices
__device__ int   g_cnt[2][NROWS];          // strict-greater counts per row
__device__ float g_colStd[4][CDIM];        // per-column std (ddof=1) of normalized feats

// ---------------------------------------------------------------- zero
__global__ void zero_kernel() {
    int i = blockIdx.x * blockDim.x + threadIdx.x;
    if (i < NROWS) {
        g_rowSum[i] = 0.f;
        g_cnt[0][i] = 0;
        g_cnt[1][i] = 0;
    }
}

// ---------------------------------------------------------------- row L2-normalize
// grid (NROWS, 4), 128 threads; each thread handles one float4 of the row.
__global__ void norm_kernel(const float* __restrict__ in0, const float* __restrict__ in1,
                            const float* __restrict__ in2, const float* __restrict__ in3) {
    int m = blockIdx.y;
    const float* in = (m == 0) ? in0 : (m == 1) ? in1 : (m == 2) ? in2 : in3;
    int r = blockIdx.x, t = threadIdx.x;
    float4 v = ((const float4*)in)[r * (CDIM / 4) + t];
    float ss = v.x * v.x + v.y * v.y + v.z * v.z + v.w * v.w;
#pragma unroll
    for (int o = 16; o; o >>= 1) ss += __shfl_down_sync(0xFFFFFFFFu, ss, o);
    __shared__ float red[4];
    if ((t & 31) == 0) red[t >> 5] = ss;
    __syncthreads();
    float tot = red[0] + red[1] + red[2] + red[3];
    float inv = 1.f / fmaxf(sqrtf(tot), 1e-12f);
    float4 o4 = make_float4(v.x * inv, v.y * inv, v.z * inv, v.w * inv);
    ((float4*)g_n[m])[r * (CDIM / 4) + t] = o4;
}

// ---------------------------------------------------------------- diagonals
// diag_v[i] = vn[i]·ptn[i], diag_t[i] = tn[i]·pvn[i]
__global__ void diag_kernel() {
    int r = blockIdx.x, t = threadIdx.x;
    float4 a = ((const float4*)g_n[0])[r * (CDIM / 4) + t];
    float4 b = ((const float4*)g_n[3])[r * (CDIM / 4) + t];
    float4 c = ((const float4*)g_n[1])[r * (CDIM / 4) + t];
    float4 d = ((const float4*)g_n[2])[r * (CDIM / 4) + t];
    float d0 = a.x * b.x + a.y * b.y + a.z * b.z + a.w * b.w;
    float d1 = c.x * d.x + c.y * d.y + c.z * d.z + c.w * d.w;
#pragma unroll
    for (int o = 16; o; o >>= 1) {
        d0 += __shfl_down_sync(0xFFFFFFFFu, d0, o);
        d1 += __shfl_down_sync(0xFFFFFFFFu, d1, o);
    }
    __shared__ float r0[4], r1[4];
    if ((t & 31) == 0) { r0[t >> 5] = d0; r1[t >> 5] = d1; }
    __syncthreads();
    if (t == 0) {
        g_diag[0][r] = r0[0] + r0[1] + r0[2] + r0[3];
        g_diag[1][r] = r1[0] + r1[1] + r1[2] + r1[3];
    }
}

// ---------------------------------------------------------------- per-column std (ddof=1)
// grid (CDIM/32, 4); block 256 = 32 cols x 8 row-strides (coalesced 128B reads).
__global__ void std_kernel() {
    int mat = blockIdx.y;
    const float* M = g_n[mat];
    int tx = threadIdx.x & 31, tg = threadIdx.x >> 5;
    int c = blockIdx.x * 32 + tx;
    float s = 0.f, sq = 0.f;
    for (int r = tg; r < NROWS; r += 8) {
        float v = M[r * CDIM + c];
        s += v;
        sq = fmaf(v, v, sq);
    }
    __shared__ float ss[8][32], qq[8][32];
    ss[tg][tx] = s;
    qq[tg][tx] = sq;
    __syncthreads();
    if (tg == 0) {
#pragma unroll
        for (int g = 1; g < 8; g++) { s += ss[g][tx]; sq += qq[g][tx]; }
        float mean = s * (1.f / (float)NROWS);
        float var = (sq - s * mean) * (1.f / (float)(NROWS - 1));
        g_colStd[mat][c] = sqrtf(fmaxf(var, 0.f));
    }
}

// ---------------------------------------------------------------- fused GEMM + epilogue
// z=0: sv = vn @ ptn^T ; z=1: st = tn @ pvn^T.
// Per row: accumulate sum exp(10*raw - 10) (shared denominator across z) and
// strict-greater-than-diagonal count (per z), with j==i excluded explicitly.
__global__ __launch_bounds__(256) void gemm_kernel() {
    __shared__ __align__(16) float sA[BK][BM + 4];
    __shared__ __align__(16) float sB[BK][BN + 4];

    int z = blockIdx.z;
    const float* __restrict__ A = g_n[z ? 1 : 0];
    const float* __restrict__ B = g_n[z ? 2 : 3];
    const float* __restrict__ dgp = g_diag[z];
    int* cnt = g_cnt[z];

    int tid = threadIdx.x;
    int tx = tid & 15, ty = tid >> 4;
    int rowBase = blockIdx.y * BM, colBase = blockIdx.x * BN;

    int lr = tid >> 2;           // 0..63
    int lk = (tid & 3) << 2;     // 0,4,8,12
    const float* aPtr = A + (rowBase + lr) * CDIM + lk;
    const float* bPtr = B + (colBase + lr) * CDIM + lk;

    float acc[4][4];
#pragma unroll
    for (int i = 0; i < 4; i++)
#pragma unroll
        for (int j = 0; j < 4; j++) acc[i][j] = 0.f;

    for (int k0 = 0; k0 < CDIM; k0 += BK) {
        float4 a4 = *(const float4*)(aPtr + k0);
        float4 b4 = *(const float4*)(bPtr + k0);
        __syncthreads();
        sA[lk + 0][lr] = a4.x; sA[lk + 1][lr] = a4.y;
        sA[lk + 2][lr] = a4.z; sA[lk + 3][lr] = a4.w;
        sB[lk + 0][lr] = b4.x; sB[lk + 1][lr] = b4.y;
        sB[lk + 2][lr] = b4.z; sB[lk + 3][lr] = b4.w;
        __syncthreads();
#pragma unroll
        for (int k = 0; k < BK; k++) {
            float4 ra = *(const float4*)&sA[k][ty << 2];
            float4 rb = *(const float4*)&sB[k][tx << 2];
            float ar[4] = {ra.x, ra.y, ra.z, ra.w};
            float br[4] = {rb.x, rb.y, rb.z, rb.w};
#pragma unroll
            for (int i = 0; i < 4; i++)
#pragma unroll
                for (int j = 0; j < 4; j++)
                    acc[i][j] = fmaf(ar[i], br[j], acc[i][j]);
        }
    }

    // Epilogue: per-row exp-sum + count, reduced across the 16 tx lanes.
#pragma unroll
    for (int tm = 0; tm < 4; tm++) {
        int r = rowBase + (ty << 2) + tm;
        float dv = dgp[r];
        float es = 0.f;
        int cc = 0;
#pragma unroll
        for (int tn = 0; tn < 4; tn++) {
            float a = acc[tm][tn];
            es += __expf(fmaf(a, 10.f, -10.f));     // bounded: arg in [-20, 0]
            int cj = colBase + (tx << 2) + tn;
            cc += (a > dv) && (cj != r);
        }
#pragma unroll
        for (int o = 8; o; o >>= 1) {
            es += __shfl_down_sync(0xFFFFFFFFu, es, o, 16);
            cc += __shfl_down_sync(0xFFFFFFFFu, cc, o, 16);
        }
        if (tx == 0) {
            atomicAdd(&g_rowSum[r], es);
            atomicAdd(&cnt[r], cc);
        }
    }
}

// ---------------------------------------------------------------- final reduction -> 13 outputs
__global__ void final_kernel(float* __restrict__ out) {
    int t = threadIdx.x;
    float acc[14];
#pragma unroll
    for (int i = 0; i < 14; i++) acc[i] = 0.f;

    for (int i = t; i < NROWS; i += 256) {
        acc[0] += logf(g_rowSum[i]);  // denominator_i = 10 + log(S_i)
        acc[1] += __expf(fmaf(g_diag[0][i], 10.f, -10.f)) +
                  __expf(fmaf(g_diag[1][i], 10.f, -10.f));
        int cv = g_cnt[0][i];
        acc[2] += (cv < 1); acc[3] += (cv < 5); acc[4] += (cv < 10); acc[5] += (float)cv;
        int ct = g_cnt[1][i];
        acc[6] += (ct < 1); acc[7] += (ct < 5); acc[8] += (ct < 10); acc[9] += (float)ct;
    }
    for (int i = t; i < CDIM; i += 256) {
        acc[10] += g_colStd[0][i];
        acc[11] += g_colStd[1][i];
        acc[12] += g_colStd[2][i];
        acc[13] += g_colStd[3][i];
    }

    __shared__ float sbuf[256];
    __shared__ float tot[14];
    for (int k = 0; k < 14; k++) {
        sbuf[t] = acc[k];
        __syncthreads();
        for (int s = 128; s; s >>= 1) {
            if (t < s) sbuf[t] += sbuf[t + s];
            __syncthreads();
        }
        if (t == 0) tot[k] = sbuf[0];
        __syncthreads();
    }

    if (t == 0) {
        float invN = 1.f / (float)NROWS;
        float den_mean = 10.f + tot[0] * invN;
        float nominator = 10.f + logf(tot[1]);
        out[0]  = den_mean - nominator;       // loss
        out[1]  = tot[10] * (1.f / (float)CDIM);  // v_std
        out[2]  = tot[11] * (1.f / (float)CDIM);  // t_std
        out[3]  = tot[12] * (1.f / (float)CDIM);  // pv_std
        out[4]  = tot[13] * (1.f / (float)CDIM);  // pt_std
        out[5]  = tot[2] * invN;  // v_r1
        out[6]  = tot[3] * invN;  // v_r5
        out[7]  = tot[4] * invN;  // v_r10
        out[8]  = tot[5] * invN;  // v_mr
        out[9]  = tot[6] * invN;  // t_r1
        out[10] = tot[7] * invN;  // t_r5
        out[11] = tot[8] * invN;  // t_r10
        out[12] = tot[9] * invN;  // t_mr
    }
}

// ---------------------------------------------------------------- launch
extern "C" void kernel_launch(void* const* d_in, const int* in_sizes, int n_in,
                              void* d_out, int out_size) {
    (void)in_sizes; (void)n_in; (void)out_size;
    const float* v  = (const float*)d_in[0];
    const float* t  = (const float*)d_in[1];
    const float* pv = (const float*)d_in[2];
    const float* pt = (const float*)d_in[3];
    float* out = (float*)d_out;

    zero_kernel<<<16, 256>>>();
    norm_kernel<<<dim3(NROWS, 4), 128>>>(v, t, pv, pt);
    diag_kernel<<<NROWS, 128>>>();
    std_kernel<<<dim3(CDIM / 32, 4), 256>>>();
    gemm_kernel<<<dim3(NROWS / BN, NROWS / BM, 2), 256>>>();
    final_kernel<<<1, 256>>>(out);
}

// round 10
// speedup vs baseline: 1.6637x; 1.6637x over previous
#include <cuda_runtime.h>

#define NROWS 4096
#define CDIM  512
#define GBM 128
#define GBN 128
#define GBK 16

// Scratch (static device globals: no allocation anywhere)
__device__ float g_n[4][NROWS * CDIM];     // normalized: 0=vn 1=tn 2=pvn 3=ptn
__device__ float g_diag[2][NROWS];         // 0: diag(sv_raw), 1: diag(st_raw)
__device__ float g_rowSum[NROWS];          // sum_j exp(10*raw - 10) over BOTH matrices
__device__ int   g_cnt[2][NROWS];          // strict-greater counts per row
__device__ float g_partS[4][4][CDIM];      // [z-rowchunk][mat][col] partial col sums
__device__ float g_partQ[4][4][CDIM];      // partial col sum-of-squares

// ---------------------------------------------------------------- f32x2 helpers
__device__ __forceinline__ void fma2(unsigned long long& d,
                                     unsigned long long a, unsigned long long b) {
    asm("fma.rn.f32x2 %0, %1, %2, %0;" : "+l"(d) : "l"(a), "l"(b));
}
__device__ __forceinline__ void unpack2(unsigned long long p, float& lo, float& hi) {
    asm("mov.b64 {%0, %1}, %2;" : "=f"(lo), "=f"(hi) : "l"(p));
}

// ---------------------------------------------------------------- zero
__global__ void zero_kernel() {
    int i = blockIdx.x * blockDim.x + threadIdx.x;
    if (i < NROWS) {
        g_rowSum[i] = 0.f;
        g_cnt[0][i] = 0;
        g_cnt[1][i] = 0;
    }
}

// ---------------------------------------------------------------- row L2-normalize
__global__ void norm_kernel(const float* __restrict__ in0, const float* __restrict__ in1,
                            const float* __restrict__ in2, const float* __restrict__ in3) {
    int m = blockIdx.y;
    const float* in = (m == 0) ? in0 : (m == 1) ? in1 : (m == 2) ? in2 : in3;
    int r = blockIdx.x, t = threadIdx.x;
    float4 v = ((const float4*)in)[r * (CDIM / 4) + t];
    float ss = v.x * v.x + v.y * v.y + v.z * v.z + v.w * v.w;
#pragma unroll
    for (int o = 16; o; o >>= 1) ss += __shfl_down_sync(0xFFFFFFFFu, ss, o);
    __shared__ float red[4];
    if ((t & 31) == 0) red[t >> 5] = ss;
    __syncthreads();
    float tot = red[0] + red[1] + red[2] + red[3];
    float inv = 1.f / fmaxf(sqrtf(tot), 1e-12f);
    float4 o4 = make_float4(v.x * inv, v.y * inv, v.z * inv, v.w * inv);
    ((float4*)g_n[m])[r * (CDIM / 4) + t] = o4;
}

// ---------------------------------------------------------------- diagonals
__global__ void diag_kernel() {
    int r = blockIdx.x, t = threadIdx.x;
    float4 a = ((const float4*)g_n[0])[r * (CDIM / 4) + t];
    float4 b = ((const float4*)g_n[3])[r * (CDIM / 4) + t];
    float4 c = ((const float4*)g_n[1])[r * (CDIM / 4) + t];
    float4 d = ((const float4*)g_n[2])[r * (CDIM / 4) + t];
    float d0 = a.x * b.x + a.y * b.y + a.z * b.z + a.w * b.w;
    float d1 = c.x * d.x + c.y * d.y + c.z * d.z + c.w * d.w;
#pragma unroll
    for (int o = 16; o; o >>= 1) {
        d0 += __shfl_down_sync(0xFFFFFFFFu, d0, o);
        d1 += __shfl_down_sync(0xFFFFFFFFu, d1, o);
    }
    __shared__ float r0[4], r1[4];
    if ((t & 31) == 0) { r0[t >> 5] = d0; r1[t >> 5] = d1; }
    __syncthreads();
    if (t == 0) {
        g_diag[0][r] = r0[0] + r0[1] + r0[2] + r0[3];
        g_diag[1][r] = r1[0] + r1[1] + r1[2] + r1[3];
    }
}

// ---------------------------------------------------------------- per-column partial sums
// grid (CDIM/64, 4, 4): block covers 64 cols (16 float4-lanes) x 1024 rows (z chunk).
// float4 loads, 16 row strides per block -> deterministic partials, no atomics.
__global__ void std_kernel() {
    int mat = blockIdx.y;
    int zc = blockIdx.z;
    const float* M = g_n[mat];
    int tx = threadIdx.x & 15, tg = threadIdx.x >> 4;
    int c4 = blockIdx.x * 16 + tx;            // float4 column index
    int r0 = zc * (NROWS / 4);

    float4 s = make_float4(0.f, 0.f, 0.f, 0.f);
    float4 q = make_float4(0.f, 0.f, 0.f, 0.f);
#pragma unroll 4
    for (int r = r0 + tg; r < r0 + NROWS / 4; r += 16) {
        float4 v = ((const float4*)M)[r * (CDIM / 4) + c4];
        s.x += v.x; q.x = fmaf(v.x, v.x, q.x);
        s.y += v.y; q.y = fmaf(v.y, v.y, q.y);
        s.z += v.z; q.z = fmaf(v.z, v.z, q.z);
        s.w += v.w; q.w = fmaf(v.w, v.w, q.w);
    }
    __shared__ float4 shS[16][16], shQ[16][16];
    shS[tg][tx] = s;
    shQ[tg][tx] = q;
    __syncthreads();
#pragma unroll
    for (int o = 8; o; o >>= 1) {
        if (tg < o) {
            float4 s2 = shS[tg + o][tx], q2 = shQ[tg + o][tx];
            float4 sc = shS[tg][tx],     qc = shQ[tg][tx];
            sc.x += s2.x; sc.y += s2.y; sc.z += s2.z; sc.w += s2.w;
            qc.x += q2.x; qc.y += q2.y; qc.z += q2.z; qc.w += q2.w;
            shS[tg][tx] = sc; shQ[tg][tx] = qc;
        }
        __syncthreads();
    }
    if (tg == 0) {
        ((float4*)g_partS[zc][mat])[c4] = shS[0][tx];
        ((float4*)g_partQ[zc][mat])[c4] = shQ[0][tx];
    }
}

// ---------------------------------------------------------------- fused GEMM + epilogue
// 128x128x16 tile, 256 threads, 8x8 per thread, packed fma.rn.f32x2 (FFMA2).
// A stored PRE-DUPLICATED in shared ((a,a) pairs -> broadcast loads, zero pack cost);
// B pairs read directly as 128-bit loads of consecutive columns.
__global__ __launch_bounds__(256, 2) void gemm_kernel() {
    __shared__ __align__(16) float sAdup[GBK][2 * GBM + 4];  // [k][2m..2m+1] = (a,a)
    __shared__ __align__(16) float sB[GBK][GBN + 4];

    int z = blockIdx.z;
    const float* __restrict__ A = g_n[z ? 1 : 0];
    const float* __restrict__ B = g_n[z ? 2 : 3];
    const float* __restrict__ dgp = g_diag[z];
    int* cnt = g_cnt[z];

    int tid = threadIdx.x;
    int tx = tid & 15, ty = tid >> 4;
    int rowBase = blockIdx.y * GBM, colBase = blockIdx.x * GBN;

    int lRow = tid >> 1;           // 0..127
    int lK   = (tid & 1) << 3;     // 0 or 8
    const float* aPtr = A + (rowBase + lRow) * CDIM + lK;
    const float* bPtr = B + (colBase + lRow) * CDIM + lK;

    unsigned long long acc[8][4];  // [row i][col-pair j] -> cols (2j, 2j+1)
#pragma unroll
    for (int i = 0; i < 8; i++)
#pragma unroll
        for (int j = 0; j < 4; j++) acc[i][j] = 0ull;

    for (int k0 = 0; k0 < CDIM; k0 += GBK) {
        float4 a0 = *(const float4*)(aPtr + k0);
        float4 a1 = *(const float4*)(aPtr + k0 + 4);
        float4 b0 = *(const float4*)(bPtr + k0);
        float4 b1 = *(const float4*)(bPtr + k0 + 4);
        __syncthreads();
        *(float2*)&sAdup[lK + 0][2 * lRow] = make_float2(a0.x, a0.x);
        *(float2*)&sAdup[lK + 1][2 * lRow] = make_float2(a0.y, a0.y);
        *(float2*)&sAdup[lK + 2][2 * lRow] = make_float2(a0.z, a0.z);
        *(float2*)&sAdup[lK + 3][2 * lRow] = make_float2(a0.w, a0.w);
        *(float2*)&sAdup[lK + 4][2 * lRow] = make_float2(a1.x, a1.x);
        *(float2*)&sAdup[lK + 5][2 * lRow] = make_float2(a1.y, a1.y);
        *(float2*)&sAdup[lK + 6][2 * lRow] = make_float2(a1.z, a1.z);
        *(float2*)&sAdup[lK + 7][2 * lRow] = make_float2(a1.w, a1.w);
        sB[lK + 0][lRow] = b0.x; sB[lK + 1][lRow] = b0.y;
        sB[lK + 2][lRow] = b0.z; sB[lK + 3][lRow] = b0.w;
        sB[lK + 4][lRow] = b1.x; sB[lK + 5][lRow] = b1.y;
        sB[lK + 6][lRow] = b1.z; sB[lK + 7][lRow] = b1.w;
        __syncthreads();

#pragma unroll
        for (int k = 0; k < GBK; k++) {
            const ulonglong2* ap = (const ulonglong2*)&sAdup[k][ty << 4];
            ulonglong2 aA = ap[0], aB = ap[1], aC = ap[2], aD = ap[3];
            const ulonglong2* bp = (const ulonglong2*)&sB[k][tx << 3];
            ulonglong2 bP = bp[0], bQ = bp[1];
            unsigned long long ad[8] = {aA.x, aA.y, aB.x, aB.y, aC.x, aC.y, aD.x, aD.y};
            unsigned long long bb[4] = {bP.x, bP.y, bQ.x, bQ.y};
#pragma unroll
            for (int i = 0; i < 8; i++)
#pragma unroll
                for (int j = 0; j < 4; j++)
                    fma2(acc[i][j], ad[i], bb[j]);
        }
    }

    // Epilogue: per-row exp-sum + strict-greater count, reduced over 16 tx lanes.
#pragma unroll
    for (int i = 0; i < 8; i++) {
        int r = rowBase + (ty << 3) + i;
        float dv = dgp[r];
        float es = 0.f;
        int cc = 0;
#pragma unroll
        for (int j = 0; j < 4; j++) {
            float lo, hi;
            unpack2(acc[i][j], lo, hi);
            int c0 = colBase + (tx << 3) + (j << 1);
            es += __expf(fmaf(lo, 10.f, -10.f));   // bounded: arg in [-20, 0]
            es += __expf(fmaf(hi, 10.f, -10.f));
            cc += (lo > dv) && (c0 != r);
            cc += (hi > dv) && (c0 + 1 != r);
        }
#pragma unroll
        for (int o = 8; o; o >>= 1) {
            es += __shfl_down_sync(0xFFFFFFFFu, es, o, 16);
            cc += __shfl_down_sync(0xFFFFFFFFu, cc, o, 16);
        }
        if (tx == 0) {
            atomicAdd(&g_rowSum[r], es);
            atomicAdd(&cnt[r], cc);
        }
    }
}

// ---------------------------------------------------------------- final reduction -> 13 outputs
__global__ void final_kernel(float* __restrict__ out) {
    int t = threadIdx.x;
    float acc[14];
#pragma unroll
    for (int i = 0; i < 14; i++) acc[i] = 0.f;

    for (int i = t; i < NROWS; i += 256) {
        acc[0] += logf(g_rowSum[i]);  // denominator_i = 10 + log(S_i)
        acc[1] += __expf(fmaf(g_diag[0][i], 10.f, -10.f)) +
                  __expf(fmaf(g_diag[1][i], 10.f, -10.f));
        int cv = g_cnt[0][i];
        acc[2] += (cv < 1); acc[3] += (cv < 5); acc[4] += (cv < 10); acc[5] += (float)cv;
        int ct = g_cnt[1][i];
        acc[6] += (ct < 1); acc[7] += (ct < 5); acc[8] += (ct < 10); acc[9] += (float)ct;
    }
    for (int i = t; i < CDIM; i += 256) {
#pragma unroll
        for (int mat = 0; mat < 4; mat++) {
            float s = 0.f, q = 0.f;
#pragma unroll
            for (int zc = 0; zc < 4; zc++) {
                s += g_partS[zc][mat][i];
                q += g_partQ[zc][mat][i];
            }
            float mean = s * (1.f / (float)NROWS);
            float var = (q - s * mean) * (1.f / (float)(NROWS - 1));
            acc[10 + mat] += sqrtf(fmaxf(var, 0.f));
        }
    }

    __shared__ float sbuf[256];
    __shared__ float tot[14];
    for (int k = 0; k < 14; k++) {
        sbuf[t] = acc[k];
        __syncthreads();
        for (int s = 128; s; s >>= 1) {
            if (t < s) sbuf[t] += sbuf[t + s];
            __syncthreads();
        }
        if (t == 0) tot[k] = sbuf[0];
        __syncthreads();
    }

    if (t == 0) {
        float invN = 1.f / (float)NROWS;
        float den_mean = 10.f + tot[0] * invN;
        float nominator = 10.f + logf(tot[1]);
        out[0]  = den_mean - nominator;           // loss
        out[1]  = tot[10] * (1.f / (float)CDIM);  // v_std
        out[2]  = tot[11] * (1.f / (float)CDIM);  // t_std
        out[3]  = tot[12] * (1.f / (float)CDIM);  // pv_std
        out[4]  = tot[13] * (1.f / (float)CDIM);  // pt_std
        out[5]  = tot[2] * invN;  // v_r1
        out[6]  = tot[3] * invN;  // v_r5
        out[7]  = tot[4] * invN;  // v_r10
        out[8]  = tot[5] * invN;  // v_mr
        out[9]  = tot[6] * invN;  // t_r1
        out[10] = tot[7] * invN;  // t_r5
        out[11] = tot[8] * invN;  // t_r10
        out[12] = tot[9] * invN;  // t_mr
    }
}

// ---------------------------------------------------------------- launch
extern "C" void kernel_launch(void* const* d_in, const int* in_sizes, int n_in,
                              void* d_out, int out_size) {
    (void)in_sizes; (void)n_in; (void)out_size;
    const float* v  = (const float*)d_in[0];
    const float* t  = (const float*)d_in[1];
    const float* pv = (const float*)d_in[2];
    const float* pt = (const float*)d_in[3];
    float* out = (float*)d_out;

    zero_kernel<<<16, 256>>>();
    norm_kernel<<<dim3(NROWS, 4), 128>>>(v, t, pv, pt);
    diag_kernel<<<NROWS, 128>>>();
    std_kernel<<<dim3(CDIM / 64, 4, 4), 256>>>();
    gemm_kernel<<<dim3(NROWS / GBN, NROWS / GBM, 2), 256>>>();
    final_kernel<<<1, 256>>>(out);
}

// round 16
// speedup vs baseline: 5.1611x; 3.1022x over previous
#include <cuda_runtime.h>
#include <cuda_bf16.h>
#include <cstdint>

#define NROWS 4096
#define CDIM  512
#define TM 128
#define TN 128
#define KC 64                    // k-chunk: 64 bf16 = 128B rows (SW128 atom)
#define NCHUNK (CDIM / KC)       // 8

// Scratch (static device globals: no allocation anywhere)
__device__ float         g_n[4][NROWS * CDIM];    // normalized fp32 (std/diag)
__device__ __nv_bfloat16 g_bh[4][NROWS * CDIM];   // bf16 hi split
__device__ __nv_bfloat16 g_bl[4][NROWS * CDIM];   // bf16 lo split (residual)
__device__ float g_diag[2][NROWS];
__device__ float g_rowSum[NROWS];
__device__ int   g_cnt[2][NROWS];
__device__ float g_partS[4][4][CDIM];
__device__ float g_partQ[4][4][CDIM];

// ------------------------------------------------------------------ PTX helpers (base ISA only)
__device__ __forceinline__ uint32_t smem_u32(const void* p) {
    uint32_t a;
    asm("{ .reg .u64 t; cvta.to.shared.u64 t, %1; cvt.u32.u64 %0, t; }" : "=r"(a) : "l"(p));
    return a;
}
__device__ __forceinline__ void cpa16(uint32_t dst, const void* src) {
    asm volatile("cp.async.cg.shared.global [%0], [%1], 16;" :: "r"(dst), "l"(src) : "memory");
}
__device__ __forceinline__ void cpa_commit() {
    asm volatile("cp.async.commit_group;" ::: "memory");
}
__device__ __forceinline__ void cpa_wait1() {
    asm volatile("cp.async.wait_group 1;" ::: "memory");
}
__device__ __forceinline__ void cpa_wait0() {
    asm volatile("cp.async.wait_group 0;" ::: "memory");
}
__device__ __forceinline__ void ldm4(uint32_t* r, uint32_t addr) {
    asm volatile("ldmatrix.sync.aligned.m8n8.x4.shared.b16 {%0,%1,%2,%3}, [%4];"
                 : "=r"(r[0]), "=r"(r[1]), "=r"(r[2]), "=r"(r[3]) : "r"(addr));
}
__device__ __forceinline__ void mma16816(float* d, const uint32_t* a, const uint32_t* b) {
    asm volatile(
        "mma.sync.aligned.m16n8k16.row.col.f32.bf16.bf16.f32 "
        "{%0,%1,%2,%3}, {%4,%5,%6,%7}, {%8,%9}, {%0,%1,%2,%3};"
        : "+f"(d[0]), "+f"(d[1]), "+f"(d[2]), "+f"(d[3])
        : "r"(a[0]), "r"(a[1]), "r"(a[2]), "r"(a[3]), "r"(b[0]), "r"(b[1]));
}

#define SW128(off) ((off) ^ (((off) >> 3) & 0x70))

// ------------------------------------------------------------------ zero
__global__ void zero_kernel() {
    int i = blockIdx.x * blockDim.x + threadIdx.x;
    if (i < NROWS) {
        g_rowSum[i] = 0.f;
        g_cnt[0][i] = 0;
        g_cnt[1][i] = 0;
    }
}

// ------------------------------------------------------------------ normalize + bf16 split
__global__ void norm_kernel(const float* __restrict__ in0, const float* __restrict__ in1,
                            const float* __restrict__ in2, const float* __restrict__ in3) {
    int m = blockIdx.y;
    const float* in = (m == 0) ? in0 : (m == 1) ? in1 : (m == 2) ? in2 : in3;
    int r = blockIdx.x, t = threadIdx.x;
    float4 v = ((const float4*)in)[r * (CDIM / 4) + t];
    float ss = v.x * v.x + v.y * v.y + v.z * v.z + v.w * v.w;
#pragma unroll
    for (int o = 16; o; o >>= 1) ss += __shfl_down_sync(0xFFFFFFFFu, ss, o);
    __shared__ float red[4];
    if ((t & 31) == 0) red[t >> 5] = ss;
    __syncthreads();
    float tot = red[0] + red[1] + red[2] + red[3];
    float inv = 1.f / fmaxf(sqrtf(tot), 1e-12f);
    float e[4] = {v.x * inv, v.y * inv, v.z * inv, v.w * inv};
    ((float4*)g_n[m])[r * (CDIM / 4) + t] = make_float4(e[0], e[1], e[2], e[3]);

    __nv_bfloat16 hi[4], lo[4];
#pragma unroll
    for (int i = 0; i < 4; i++) {
        hi[i] = __float2bfloat16(e[i]);
        lo[i] = __float2bfloat16(e[i] - __bfloat162float(hi[i]));
    }
    __nv_bfloat162* ph = (__nv_bfloat162*)g_bh[m];
    __nv_bfloat162* pl = (__nv_bfloat162*)g_bl[m];
    int b = r * (CDIM / 2) + 2 * t;
    ph[b]     = __nv_bfloat162(hi[0], hi[1]);
    ph[b + 1] = __nv_bfloat162(hi[2], hi[3]);
    pl[b]     = __nv_bfloat162(lo[0], lo[1]);
    pl[b + 1] = __nv_bfloat162(lo[2], lo[3]);
}

// ------------------------------------------------------------------ diagonals (fp32 exact)
__global__ void diag_kernel() {
    int r = blockIdx.x, t = threadIdx.x;
    float4 a = ((const float4*)g_n[0])[r * (CDIM / 4) + t];
    float4 b = ((const float4*)g_n[3])[r * (CDIM / 4) + t];
    float4 c = ((const float4*)g_n[1])[r * (CDIM / 4) + t];
    float4 d = ((const float4*)g_n[2])[r * (CDIM / 4) + t];
    float d0 = a.x * b.x + a.y * b.y + a.z * b.z + a.w * b.w;
    float d1 = c.x * d.x + c.y * d.y + c.z * d.z + c.w * d.w;
#pragma unroll
    for (int o = 16; o; o >>= 1) {
        d0 += __shfl_down_sync(0xFFFFFFFFu, d0, o);
        d1 += __shfl_down_sync(0xFFFFFFFFu, d1, o);
    }
    __shared__ float r0[4], r1[4];
    if ((t & 31) == 0) { r0[t >> 5] = d0; r1[t >> 5] = d1; }
    __syncthreads();
    if (t == 0) {
        g_diag[0][r] = r0[0] + r0[1] + r0[2] + r0[3];
        g_diag[1][r] = r1[0] + r1[1] + r1[2] + r1[3];
    }
}

// ------------------------------------------------------------------ per-column partial sums
__global__ void std_kernel() {
    int mat = blockIdx.y;
    int zc = blockIdx.z;
    const float* M = g_n[mat];
    int tx = threadIdx.x & 15, tg = threadIdx.x >> 4;
    int c4 = blockIdx.x * 16 + tx;
    int r0 = zc * (NROWS / 4);

    float4 s = make_float4(0.f, 0.f, 0.f, 0.f);
    float4 q = make_float4(0.f, 0.f, 0.f, 0.f);
#pragma unroll 4
    for (int r = r0 + tg; r < r0 + NROWS / 4; r += 16) {
        float4 v = ((const float4*)M)[r * (CDIM / 4) + c4];
        s.x += v.x; q.x = fmaf(v.x, v.x, q.x);
        s.y += v.y; q.y = fmaf(v.y, v.y, q.y);
        s.z += v.z; q.z = fmaf(v.z, v.z, q.z);
        s.w += v.w; q.w = fmaf(v.w, v.w, q.w);
    }
    __shared__ float4 shS[16][16], shQ[16][16];
    shS[tg][tx] = s;
    shQ[tg][tx] = q;
    __syncthreads();
#pragma unroll
    for (int o = 8; o; o >>= 1) {
        if (tg < o) {
            float4 s2 = shS[tg + o][tx], q2 = shQ[tg + o][tx];
            float4 sc = shS[tg][tx],     qc = shQ[tg][tx];
            sc.x += s2.x; sc.y += s2.y; sc.z += s2.z; sc.w += s2.w;
            qc.x += q2.x; qc.y += q2.y; qc.z += q2.z; qc.w += q2.w;
            shS[tg][tx] = sc; shQ[tg][tx] = qc;
        }
        __syncthreads();
    }
    if (tg == 0) {
        ((float4*)g_partS[zc][mat])[c4] = shS[0][tx];
        ((float4*)g_partQ[zc][mat])[c4] = shQ[0][tx];
    }
}

// ------------------------------------------------------------------ mma.sync GEMM + epilogue
// Dynamic smem (128KB): stage b in {0,1}: [b*65536 + part*16384],
// part: 0=Ahi 1=Alo 2=Bhi 3=Blo; each 128 rows x 64 bf16 (128B rows, SW128).
#define GEMM_SMEM 131072

__device__ __forceinline__ void load_chunk(uint32_t sb, int buf, int kc,
                                           const __nv_bfloat16* Ah, const __nv_bfloat16* Al,
                                           const __nv_bfloat16* Bh, const __nv_bfloat16* Bl,
                                           int rowBase, int colBase, int tid) {
    const __nv_bfloat16* mats[4] = {Ah, Al, Bh, Bl};
    int bases[4] = {rowBase, rowBase, colBase, colBase};
#pragma unroll
    for (int p = 0; p < 4; p++) {
        const __nv_bfloat16* M = mats[p];
        int rb = bases[p];
        uint32_t dbase = sb + buf * 65536 + p * 16384;
#pragma unroll
        for (int i = 0; i < 4; i++) {
            int idx = tid + i * 256;          // 0..1023: row = idx>>3, 16B-group = idx&7
            int row = idx >> 3, cg = idx & 7;
            const void* src = M + (size_t)(rb + row) * CDIM + kc * KC + cg * 8;
            uint32_t off = (uint32_t)(row * 128 + cg * 16);
            cpa16(dbase + SW128(off), src);
        }
    }
}

__global__ __launch_bounds__(256, 1) void gemm_kernel() {
    extern __shared__ char smem[];
    uint32_t sb = smem_u32(smem);
    int tid = threadIdx.x;
    int wid = tid >> 5, lane = tid & 31;

    int z = blockIdx.z;
    const __nv_bfloat16* Ah = g_bh[z ? 1 : 0];
    const __nv_bfloat16* Al = g_bl[z ? 1 : 0];
    const __nv_bfloat16* Bh = g_bh[z ? 2 : 3];
    const __nv_bfloat16* Bl = g_bl[z ? 2 : 3];
    int rowBase = blockIdx.y * TM, colBase = blockIdx.x * TN;

    // Warp tiling: 2 (m) x 4 (n) warps; each warp 64x32 = 4x4 tiles of m16n8.
    int mBase = (wid >> 2) * 64;
    int nBase = (wid & 3) * 32;

    // ldmatrix per-lane addressing (SW128: XOR is (row&7)<<4, and row&7 == lane&7
    // for every group because tile row offsets are multiples of 8/16)
    uint32_t sw = (uint32_t)(lane & 7) << 4;
    int rowA = lane & 15;                      // A: lanes 0-15 rows, 16-31 rows @k+8
    uint32_t kbA = (uint32_t)((lane >> 4) << 4);
    int rowB = (lane & 7) | ((lane >> 4) << 3);// B: 0-7 n0..7@k, 8-15 n0..7@k+8, 16-23 n8..15@k, 24-31 @k+8
    uint32_t kbB = (uint32_t)(((lane >> 3) & 1) << 4);

    uint32_t offA[4], offB[2];
#pragma unroll
    for (int mi = 0; mi < 4; mi++) offA[mi] = (uint32_t)((mBase + mi * 16 + rowA) * 128);
#pragma unroll
    for (int nb = 0; nb < 2; nb++) offB[nb] = (uint32_t)((nBase + nb * 16 + rowB) * 128);

    float acc[4][4][4];
#pragma unroll
    for (int i = 0; i < 4; i++)
#pragma unroll
        for (int j = 0; j < 4; j++)
#pragma unroll
            for (int k = 0; k < 4; k++) acc[i][j][k] = 0.f;

    // Prologue: prefetch chunks 0 and 1
    load_chunk(sb, 0, 0, Ah, Al, Bh, Bl, rowBase, colBase, tid);
    cpa_commit();
    load_chunk(sb, 1, 1, Ah, Al, Bh, Bl, rowBase, colBase, tid);
    cpa_commit();

    for (int kc = 0; kc < NCHUNK; kc++) {
        if (kc < NCHUNK - 1) cpa_wait1(); else cpa_wait0();
        __syncthreads();

        uint32_t stage = sb + (uint32_t)(kc & 1) * 65536;
        uint32_t sAh = stage, sAl = stage + 16384, sBh = stage + 32768, sBl = stage + 49152;

#pragma unroll
        for (int ks = 0; ks < 4; ks++) {
            uint32_t kA = ((uint32_t)(ks * 32) + kbA) ^ sw;
            uint32_t kB = ((uint32_t)(ks * 32) + kbB) ^ sw;
            uint32_t bh[2][4], bl[2][4];
            ldm4(bh[0], sBh + offB[0] + kB);
            ldm4(bh[1], sBh + offB[1] + kB);
            ldm4(bl[0], sBl + offB[0] + kB);
            ldm4(bl[1], sBl + offB[1] + kB);
#pragma unroll
            for (int mi = 0; mi < 4; mi++) {
                uint32_t ah[4], al[4];
                ldm4(ah, sAh + offA[mi] + kA);
                ldm4(al, sAl + offA[mi] + kA);
#pragma unroll
                for (int ni = 0; ni < 4; ni++) {
                    const uint32_t* fBh = bh[ni >> 1] + (ni & 1) * 2;
                    const uint32_t* fBl = bl[ni >> 1] + (ni & 1) * 2;
                    mma16816(acc[mi][ni], ah, fBh);   // Ah*Bh
                    mma16816(acc[mi][ni], ah, fBl);   // Ah*Bl
                    mma16816(acc[mi][ni], al, fBh);   // Al*Bh
                }
            }
        }
        __syncthreads();
        if (kc + 2 < NCHUNK) {
            load_chunk(sb, kc & 1, kc + 2, Ah, Al, Bh, Bl, rowBase, colBase, tid);
            cpa_commit();
        }
    }

    // Epilogue: fragment c layout: thread holds rows (g, g+8), cols 2q+{0,1}
    int g = lane >> 2, q = lane & 3;
#pragma unroll
    for (int mi = 0; mi < 4; mi++) {
        int r0 = rowBase + mBase + mi * 16 + g;
        int r1 = r0 + 8;
        float dv0 = g_diag[z][r0], dv1 = g_diag[z][r1];
        float es0 = 0.f, es1 = 0.f;
        int c0 = 0, c1 = 0;
#pragma unroll
        for (int ni = 0; ni < 4; ni++) {
#pragma unroll
            for (int j = 0; j < 2; j++) {
                int col = colBase + nBase + ni * 8 + 2 * q + j;
                float a0 = acc[mi][ni][j];       // row g
                float a1 = acc[mi][ni][2 + j];   // row g+8
                es0 += __expf(fmaf(a0, 10.f, -10.f));  // bounded: arg in [-20, 0]
                es1 += __expf(fmaf(a1, 10.f, -10.f));
                c0 += (a0 > dv0) && (col != r0);
                c1 += (a1 > dv1) && (col != r1);
            }
        }
        // quad reduce (lanes sharing the same rows differ only in q)
#pragma unroll
        for (int o = 1; o <= 2; o <<= 1) {
            es0 += __shfl_xor_sync(0xFFFFFFFFu, es0, o);
            es1 += __shfl_xor_sync(0xFFFFFFFFu, es1, o);
            c0 += __shfl_xor_sync(0xFFFFFFFFu, c0, o);
            c1 += __shfl_xor_sync(0xFFFFFFFFu, c1, o);
        }
        if (q == 0) {
            atomicAdd(&g_rowSum[r0], es0);
            atomicAdd(&g_rowSum[r1], es1);
            atomicAdd(&g_cnt[z][r0], c0);
            atomicAdd(&g_cnt[z][r1], c1);
        }
    }
}

// ------------------------------------------------------------------ final reduction -> 13 outputs
__global__ void final_kernel(float* __restrict__ out) {
    int t = threadIdx.x;
    float acc[14];
#pragma unroll
    for (int i = 0; i < 14; i++) acc[i] = 0.f;

    for (int i = t; i < NROWS; i += 256) {
        acc[0] += logf(g_rowSum[i]);
        acc[1] += __expf(fmaf(g_diag[0][i], 10.f, -10.f)) +
                  __expf(fmaf(g_diag[1][i], 10.f, -10.f));
        int cv = g_cnt[0][i];
        acc[2] += (cv < 1); acc[3] += (cv < 5); acc[4] += (cv < 10); acc[5] += (float)cv;
        int ct = g_cnt[1][i];
        acc[6] += (ct < 1); acc[7] += (ct < 5); acc[8] += (ct < 10); acc[9] += (float)ct;
    }
    for (int i = t; i < CDIM; i += 256) {
#pragma unroll
        for (int mat = 0; mat < 4; mat++) {
            float s = 0.f, qq = 0.f;
#pragma unroll
            for (int zc = 0; zc < 4; zc++) {
                s += g_partS[zc][mat][i];
                qq += g_partQ[zc][mat][i];
            }
            float mean = s * (1.f / (float)NROWS);
            float var = (qq - s * mean) * (1.f / (float)(NROWS - 1));
            acc[10 + mat] += sqrtf(fmaxf(var, 0.f));
        }
    }

    __shared__ float sbuf[256];
    __shared__ float tot[14];
    for (int k = 0; k < 14; k++) {
        sbuf[t] = acc[k];
        __syncthreads();
        for (int s = 128; s; s >>= 1) {
            if (t < s) sbuf[t] += sbuf[t + s];
            __syncthreads();
        }
        if (t == 0) tot[k] = sbuf[0];
        __syncthreads();
    }

    if (t == 0) {
        float invN = 1.f / (float)NROWS;
        float den_mean = 10.f + tot[0] * invN;
        float nominator = 10.f + logf(tot[1]);
        out[0]  = den_mean - nominator;
        out[1]  = tot[10] * (1.f / (float)CDIM);
        out[2]  = tot[11] * (1.f / (float)CDIM);
        out[3]  = tot[12] * (1.f / (float)CDIM);
        out[4]  = tot[13] * (1.f / (float)CDIM);
        out[5]  = tot[2] * invN;
        out[6]  = tot[3] * invN;
        out[7]  = tot[4] * invN;
        out[8]  = tot[5] * invN;
        out[9]  = tot[6] * invN;
        out[10] = tot[7] * invN;
        out[11] = tot[8] * invN;
        out[12] = tot[9] * invN;
    }
}

// ------------------------------------------------------------------ launch
extern "C" void kernel_launch(void* const* d_in, const int* in_sizes, int n_in,
                              void* d_out, int out_size) {
    (void)in_sizes; (void)n_in; (void)out_size;
    const float* v  = (const float*)d_in[0];
    const float* t  = (const float*)d_in[1];
    const float* pv = (const float*)d_in[2];
    const float* pt = (const float*)d_in[3];
    float* out = (float*)d_out;

    cudaFuncSetAttribute(gemm_kernel, cudaFuncAttributeMaxDynamicSharedMemorySize,
                         GEMM_SMEM);

    zero_kernel<<<16, 256>>>();
    norm_kernel<<<dim3(NROWS, 4), 128>>>(v, t, pv, pt);
    diag_kernel<<<NROWS, 128>>>();
    std_kernel<<<dim3(CDIM / 64, 4, 4), 256>>>();
    gemm_kernel<<<dim3(NROWS / TN, NROWS / TM, 2), 256, GEMM_SMEM>>>();
    final_kernel<<<1, 256>>>(out);
}

// round 17
// speedup vs baseline: 5.1939x; 1.0064x over previous
#include <cuda_runtime.h>
#include <cuda_bf16.h>
#include <cstdint>

#define NROWS 4096
#define CDIM  512
#define TM 128
#define TN 128
#define KC 32                    // k-chunk: 32 bf16; row = [hi 64B | lo 64B] = 128B SW128
#define NCHUNK (CDIM / KC)       // 16
#define NZC 16                   // std row-chunks

// Scratch (static device globals: no allocation anywhere)
__device__ float         g_n[4][NROWS * CDIM];    // normalized fp32 (std)
__device__ __nv_bfloat16 g_bh[4][NROWS * CDIM];   // bf16 hi split
__device__ __nv_bfloat16 g_bl[4][NROWS * CDIM];   // bf16 lo split (residual)
__device__ float g_diag[2][NROWS];
__device__ float g_rowSum[NROWS];
__device__ int   g_cnt[2][NROWS];
__device__ float g_partS[NZC][4][CDIM];
__device__ float g_partQ[NZC][4][CDIM];

// ------------------------------------------------------------------ PTX helpers (base ISA only)
__device__ __forceinline__ uint32_t smem_u32(const void* p) {
    uint32_t a;
    asm("{ .reg .u64 t; cvta.to.shared.u64 t, %1; cvt.u32.u64 %0, t; }" : "=r"(a) : "l"(p));
    return a;
}
__device__ __forceinline__ void cpa16(uint32_t dst, const void* src) {
    asm volatile("cp.async.cg.shared.global [%0], [%1], 16;" :: "r"(dst), "l"(src) : "memory");
}
__device__ __forceinline__ void cpa_commit() {
    asm volatile("cp.async.commit_group;" ::: "memory");
}
__device__ __forceinline__ void cpa_wait1() {
    asm volatile("cp.async.wait_group 1;" ::: "memory");
}
__device__ __forceinline__ void cpa_wait0() {
    asm volatile("cp.async.wait_group 0;" ::: "memory");
}
__device__ __forceinline__ void ldm4(uint32_t* r, uint32_t addr) {
    asm volatile("ldmatrix.sync.aligned.m8n8.x4.shared.b16 {%0,%1,%2,%3}, [%4];"
                 : "=r"(r[0]), "=r"(r[1]), "=r"(r[2]), "=r"(r[3]) : "r"(addr));
}
__device__ __forceinline__ void mma16816(float* d, const uint32_t* a, const uint32_t* b) {
    asm volatile(
        "mma.sync.aligned.m16n8k16.row.col.f32.bf16.bf16.f32 "
        "{%0,%1,%2,%3}, {%4,%5,%6,%7}, {%8,%9}, {%0,%1,%2,%3};"
        : "+f"(d[0]), "+f"(d[1]), "+f"(d[2]), "+f"(d[3])
        : "r"(a[0]), "r"(a[1]), "r"(a[2]), "r"(a[3]), "r"(b[0]), "r"(b[1]));
}

#define SW128(off) ((off) ^ (((off) >> 3) & 0x70))

// ------------------------------------------------------------------ fused zero + normalize + split + diag
// grid 4096 blocks, 512 threads: group m (128 thr) handles matrix m, row r.
__global__ void norm_fused(const float* __restrict__ in0, const float* __restrict__ in1,
                           const float* __restrict__ in2, const float* __restrict__ in3) {
    int r = blockIdx.x;
    int m = threadIdx.x >> 7, t = threadIdx.x & 127;
    const float* in = (m == 0) ? in0 : (m == 1) ? in1 : (m == 2) ? in2 : in3;

    __shared__ float sh[4][CDIM];
    __shared__ float red[4][4];
    __shared__ float redD[2][4];

    float4 v = ((const float4*)in)[r * (CDIM / 4) + t];
    float ss = v.x * v.x + v.y * v.y + v.z * v.z + v.w * v.w;
#pragma unroll
    for (int o = 16; o; o >>= 1) ss += __shfl_down_sync(0xFFFFFFFFu, ss, o);
    if ((t & 31) == 0) red[m][t >> 5] = ss;
    __syncthreads();
    float tot = red[m][0] + red[m][1] + red[m][2] + red[m][3];
    float inv = 1.f / fmaxf(sqrtf(tot), 1e-12f);
    float e[4] = {v.x * inv, v.y * inv, v.z * inv, v.w * inv};
    ((float4*)g_n[m])[r * (CDIM / 4) + t] = make_float4(e[0], e[1], e[2], e[3]);
    ((float4*)sh[m])[t] = make_float4(e[0], e[1], e[2], e[3]);

    __nv_bfloat16 hi[4], lo[4];
#pragma unroll
    for (int i = 0; i < 4; i++) {
        hi[i] = __float2bfloat16(e[i]);
        lo[i] = __float2bfloat16(e[i] - __bfloat162float(hi[i]));
    }
    __nv_bfloat162* ph = (__nv_bfloat162*)g_bh[m];
    __nv_bfloat162* pl = (__nv_bfloat162*)g_bl[m];
    int b = r * (CDIM / 2) + 2 * t;
    ph[b]     = __nv_bfloat162(hi[0], hi[1]);
    ph[b + 1] = __nv_bfloat162(hi[2], hi[3]);
    pl[b]     = __nv_bfloat162(lo[0], lo[1]);
    pl[b + 1] = __nv_bfloat162(lo[2], lo[3]);
    __syncthreads();

    if (m == 0) {
        float4 a = ((const float4*)sh[0])[t];
        float4 d = ((const float4*)sh[3])[t];
        float4 c = ((const float4*)sh[1])[t];
        float4 p = ((const float4*)sh[2])[t];
        float d0 = a.x * d.x + a.y * d.y + a.z * d.z + a.w * d.w;
        float d1 = c.x * p.x + c.y * p.y + c.z * p.z + c.w * p.w;
#pragma unroll
        for (int o = 16; o; o >>= 1) {
            d0 += __shfl_down_sync(0xFFFFFFFFu, d0, o);
            d1 += __shfl_down_sync(0xFFFFFFFFu, d1, o);
        }
        if ((t & 31) == 0) { redD[0][t >> 5] = d0; redD[1][t >> 5] = d1; }
    }
    __syncthreads();
    if (threadIdx.x == 0) {
        g_diag[0][r] = redD[0][0] + redD[0][1] + redD[0][2] + redD[0][3];
        g_diag[1][r] = redD[1][0] + redD[1][1] + redD[1][2] + redD[1][3];
        g_rowSum[r] = 0.f;
        g_cnt[0][r] = 0;
        g_cnt[1][r] = 0;
    }
}

// ------------------------------------------------------------------ per-column partial sums
// grid (CDIM/64, 4, NZC): block = 64 cols (16 float4-lanes) x 256 rows.
__global__ void std_kernel() {
    int mat = blockIdx.y;
    int zc = blockIdx.z;
    const float* M = g_n[mat];
    int tx = threadIdx.x & 15, tg = threadIdx.x >> 4;
    int c4 = blockIdx.x * 16 + tx;
    int r0 = zc * (NROWS / NZC);

    float4 s = make_float4(0.f, 0.f, 0.f, 0.f);
    float4 q = make_float4(0.f, 0.f, 0.f, 0.f);
#pragma unroll 4
    for (int r = r0 + tg; r < r0 + NROWS / NZC; r += 16) {
        float4 v = ((const float4*)M)[r * (CDIM / 4) + c4];
        s.x += v.x; q.x = fmaf(v.x, v.x, q.x);
        s.y += v.y; q.y = fmaf(v.y, v.y, q.y);
        s.z += v.z; q.z = fmaf(v.z, v.z, q.z);
        s.w += v.w; q.w = fmaf(v.w, v.w, q.w);
    }
    __shared__ float4 shS[16][16], shQ[16][16];
    shS[tg][tx] = s;
    shQ[tg][tx] = q;
    __syncthreads();
#pragma unroll
    for (int o = 8; o; o >>= 1) {
        if (tg < o) {
            float4 s2 = shS[tg + o][tx], q2 = shQ[tg + o][tx];
            float4 sc = shS[tg][tx],     qc = shQ[tg][tx];
            sc.x += s2.x; sc.y += s2.y; sc.z += s2.z; sc.w += s2.w;
            qc.x += q2.x; qc.y += q2.y; qc.z += q2.z; qc.w += q2.w;
            shS[tg][tx] = sc; shQ[tg][tx] = qc;
        }
        __syncthreads();
    }
    if (tg == 0) {
        ((float4*)g_partS[zc][mat])[c4] = shS[0][tx];
        ((float4*)g_partQ[zc][mat])[c4] = shQ[0][tx];
    }
}

// ------------------------------------------------------------------ mma.sync GEMM + epilogue
// Dynamic smem (64KB): stage s in {0,1} at s*32768: A tile 16KB then B tile 16KB.
// Tile row (128B, SW128): bytes [0,64) = hi for 32 k-values, bytes [64,128) = lo.
#define GEMM_SMEM 65536

__device__ __forceinline__ void load_chunk(uint32_t sb, int buf, int kc,
                                           const __nv_bfloat16* Ah, const __nv_bfloat16* Al,
                                           const __nv_bfloat16* Bh, const __nv_bfloat16* Bl,
                                           int rowBase, int colBase, int tid) {
#pragma unroll
    for (int p = 0; p < 2; p++) {
        const __nv_bfloat16* Mh = p ? Bh : Ah;
        const __nv_bfloat16* Ml = p ? Bl : Al;
        int rb = p ? colBase : rowBase;
        uint32_t dbase = sb + (uint32_t)buf * 32768 + (uint32_t)p * 16384;
#pragma unroll
        for (int i = 0; i < 4; i++) {
            int idx = tid + i * 256;          // 0..1023: row = idx>>3, cg = idx&7
            int row = idx >> 3, cg = idx & 7;
            const __nv_bfloat16* M = (cg < 4) ? Mh : Ml;
            int k = kc * KC + (cg & 3) * 8;
            const void* src = M + (size_t)(rb + row) * CDIM + k;
            uint32_t off = (uint32_t)(row * 128 + cg * 16);
            cpa16(dbase + SW128(off), src);
        }
    }
}

__global__ __launch_bounds__(256, 2) void gemm_kernel() {
    extern __shared__ char smem[];
    uint32_t sb = smem_u32(smem);
    int tid = threadIdx.x;
    int wid = tid >> 5, lane = tid & 31;

    int z = blockIdx.z;
    const __nv_bfloat16* Ah = g_bh[z ? 1 : 0];
    const __nv_bfloat16* Al = g_bl[z ? 1 : 0];
    const __nv_bfloat16* Bh = g_bh[z ? 2 : 3];
    const __nv_bfloat16* Bl = g_bl[z ? 2 : 3];
    int rowBase = blockIdx.y * TM, colBase = blockIdx.x * TN;

    // Warp tiling: 2 (m) x 4 (n) warps; each warp 64x32 = 4x4 tiles of m16n8.
    int mBase = (wid >> 2) * 64;
    int nBase = (wid & 3) * 32;

    uint32_t sw = (uint32_t)(lane & 7) << 4;
    int rowA = lane & 15;
    uint32_t kbA = (uint32_t)((lane >> 4) << 4);
    int rowB = (lane & 7) | ((lane >> 4) << 3);
    uint32_t kbB = (uint32_t)(((lane >> 3) & 1) << 4);

    uint32_t offA[4], offB[2];
#pragma unroll
    for (int mi = 0; mi < 4; mi++) offA[mi] = (uint32_t)((mBase + mi * 16 + rowA) * 128);
#pragma unroll
    for (int nb = 0; nb < 2; nb++) offB[nb] = (uint32_t)((nBase + nb * 16 + rowB) * 128);

    float acc[4][4][4];
#pragma unroll
    for (int i = 0; i < 4; i++)
#pragma unroll
        for (int j = 0; j < 4; j++)
#pragma unroll
            for (int k = 0; k < 4; k++) acc[i][j][k] = 0.f;

    // Prologue: prefetch chunks 0 and 1
    load_chunk(sb, 0, 0, Ah, Al, Bh, Bl, rowBase, colBase, tid);
    cpa_commit();
    load_chunk(sb, 1, 1, Ah, Al, Bh, Bl, rowBase, colBase, tid);
    cpa_commit();

    for (int kc = 0; kc < NCHUNK; kc++) {
        if (kc < NCHUNK - 1) cpa_wait1(); else cpa_wait0();
        __syncthreads();

        uint32_t stage = sb + (uint32_t)(kc & 1) * 32768;
        uint32_t sA = stage, sB = stage + 16384;

#pragma unroll
        for (int ks = 0; ks < 2; ks++) {
            uint32_t hA = (uint32_t)(ks * 32) + kbA;          // hi byte offset (<64)
            uint32_t hB = (uint32_t)(ks * 32) + kbB;
            uint32_t bh[2][4], bl[2][4];
            ldm4(bh[0], sB + offB[0] + (hB ^ sw));
            ldm4(bh[1], sB + offB[1] + (hB ^ sw));
            ldm4(bl[0], sB + offB[0] + ((hB + 64) ^ sw));
            ldm4(bl[1], sB + offB[1] + ((hB + 64) ^ sw));
#pragma unroll
            for (int mi = 0; mi < 4; mi++) {
                uint32_t ah[4], al[4];
                ldm4(ah, sA + offA[mi] + (hA ^ sw));
                ldm4(al, sA + offA[mi] + ((hA + 64) ^ sw));
#pragma unroll
                for (int ni = 0; ni < 4; ni++) {
                    const uint32_t* fBh = bh[ni >> 1] + (ni & 1) * 2;
                    const uint32_t* fBl = bl[ni >> 1] + (ni & 1) * 2;
                    mma16816(acc[mi][ni], ah, fBh);   // Ah*Bh
                    mma16816(acc[mi][ni], ah, fBl);   // Ah*Bl
                    mma16816(acc[mi][ni], al, fBh);   // Al*Bh
                }
            }
        }
        __syncthreads();
        if (kc + 2 < NCHUNK) {
            load_chunk(sb, kc & 1, kc + 2, Ah, Al, Bh, Bl, rowBase, colBase, tid);
            cpa_commit();
        }
    }

    // Epilogue: fragment layout: thread holds rows (g, g+8), cols 2q+{0,1}
    int g = lane >> 2, q = lane & 3;
#pragma unroll
    for (int mi = 0; mi < 4; mi++) {
        int r0 = rowBase + mBase + mi * 16 + g;
        int r1 = r0 + 8;
        float dv0 = g_diag[z][r0], dv1 = g_diag[z][r1];
        float es0 = 0.f, es1 = 0.f;
        int c0 = 0, c1 = 0;
#pragma unroll
        for (int ni = 0; ni < 4; ni++) {
#pragma unroll
            for (int j = 0; j < 2; j++) {
                int col = colBase + nBase + ni * 8 + 2 * q + j;
                float a0 = acc[mi][ni][j];
                float a1 = acc[mi][ni][2 + j];
                es0 += __expf(fmaf(a0, 10.f, -10.f));  // bounded: arg in [-20, 0]
                es1 += __expf(fmaf(a1, 10.f, -10.f));
                c0 += (a0 > dv0) && (col != r0);
                c1 += (a1 > dv1) && (col != r1);
            }
        }
#pragma unroll
        for (int o = 1; o <= 2; o <<= 1) {
            es0 += __shfl_xor_sync(0xFFFFFFFFu, es0, o);
            es1 += __shfl_xor_sync(0xFFFFFFFFu, es1, o);
            c0 += __shfl_xor_sync(0xFFFFFFFFu, c0, o);
            c1 += __shfl_xor_sync(0xFFFFFFFFu, c1, o);
        }
        if (q == 0) {
            atomicAdd(&g_rowSum[r0], es0);
            atomicAdd(&g_rowSum[r1], es1);
            atomicAdd(&g_cnt[z][r0], c0);
            atomicAdd(&g_cnt[z][r1], c1);
        }
    }
}

// ------------------------------------------------------------------ final reduction -> 13 outputs
__global__ void final_kernel(float* __restrict__ out) {
    int t = threadIdx.x;
    float acc[14];
#pragma unroll
    for (int i = 0; i < 14; i++) acc[i] = 0.f;

    for (int i = t; i < NROWS; i += 256) {
        acc[0] += logf(g_rowSum[i]);
        acc[1] += __expf(fmaf(g_diag[0][i], 10.f, -10.f)) +
                  __expf(fmaf(g_diag[1][i], 10.f, -10.f));
        int cv = g_cnt[0][i];
        acc[2] += (cv < 1); acc[3] += (cv < 5); acc[4] += (cv < 10); acc[5] += (float)cv;
        int ct = g_cnt[1][i];
        acc[6] += (ct < 1); acc[7] += (ct < 5); acc[8] += (ct < 10); acc[9] += (float)ct;
    }
    for (int i = t; i < CDIM; i += 256) {
#pragma unroll
        for (int mat = 0; mat < 4; mat++) {
            float s = 0.f, qq = 0.f;
#pragma unroll
            for (int zc = 0; zc < NZC; zc++) {
                s += g_partS[zc][mat][i];
                qq += g_partQ[zc][mat][i];
            }
            float mean = s * (1.f / (float)NROWS);
            float var = (qq - s * mean) * (1.f / (float)(NROWS - 1));
            acc[10 + mat] += sqrtf(fmaxf(var, 0.f));
        }
    }

    __shared__ float sbuf[256];
    __shared__ float tot[14];
    for (int k = 0; k < 14; k++) {
        sbuf[t] = acc[k];
        __syncthreads();
        for (int s = 128; s; s >>= 1) {
            if (t < s) sbuf[t] += sbuf[t + s];
            __syncthreads();
        }
        if (t == 0) tot[k] = sbuf[0];
        __syncthreads();
    }

    if (t == 0) {
        float invN = 1.f / (float)NROWS;
        float den_mean = 10.f + tot[0] * invN;
        float nominator = 10.f + logf(tot[1]);
        out[0]  = den_mean - nominator;
        out[1]  = tot[10] * (1.f / (float)CDIM);
        out[2]  = tot[11] * (1.f / (float)CDIM);
        out[3]  = tot[12] * (1.f / (float)CDIM);
        out[4]  = tot[13] * (1.f / (float)CDIM);
        out[5]  = tot[2] * invN;
        out[6]  = tot[3] * invN;
        out[7]  = tot[4] * invN;
        out[8]  = tot[5] * invN;
        out[9]  = tot[6] * invN;
        out[10] = tot[7] * invN;
        out[11] = tot[8] * invN;
        out[12] = tot[9] * invN;
    }
}

// ------------------------------------------------------------------ launch
extern "C" void kernel_launch(void* const* d_in, const int* in_sizes, int n_in,
                              void* d_out, int out_size) {
    (void)in_sizes; (void)n_in; (void)out_size;
    const float* v  = (const float*)d_in[0];
    const float* t  = (const float*)d_in[1];
    const float* pv = (const float*)d_in[2];
    const float* pt = (const float*)d_in[3];
    float* out = (float*)d_out;

    cudaFuncSetAttribute(gemm_kernel, cudaFuncAttributeMaxDynamicSharedMemorySize,
                         GEMM_SMEM);

    norm_fused<<<NROWS, 512>>>(v, t, pv, pt);
    std_kernel<<<dim3(CDIM / 64, 4, NZC), 256>>>();
    gemm_kernel<<<dim3(NROWS / TN, NROWS / TM, 2), 256, GEMM_SMEM>>>();
    final_kernel<<<1, 256>>>(out);
}